// round 3
// baseline (speedup 1.0000x reference)
#include <cuda_runtime.h>

#define NCH 27
#define HH 64
#define WW 64
#define OC 32
#define NB 2

// packed weights: per (oc, c, ki): {w0, w1, w2, w0*w1*w2}
__device__ float4 g_wpack[OC * NCH * 3];

__global__ void pack_weights_kernel(const float* __restrict__ w) {
    int i = blockIdx.x * blockDim.x + threadIdx.x;
    if (i < OC * NCH * 3) {
        const float* p = w + i * 3;
        float a = p[0], b = p[1], c = p[2];
        g_wpack[i] = make_float4(a, b, c, a * b * c);
    }
}

__device__ __forceinline__ float maj3(float a, float b, float c) {
    // majority-gate bipolar sim for n=3: (a+b+c - a*b*c) / 2
    return 0.5f * (a + b + c - a * b * c);
}

__global__ __launch_bounds__(64) void sconv_kernel(const float* __restrict__ x,
                                                   float* __restrict__ out) {
    __shared__ float tile[NCH * 3 * 66];   // [c][row(3)][col(66: w=-1..64)]
    __shared__ float4 wsh[NCH * 3];

    const int h  = blockIdx.x;
    const int oc = blockIdx.y;
    const int n  = blockIdx.z;
    const int tid = threadIdx.x;

    // weights for this oc (uniform across block -> broadcast reads later)
    for (int i = tid; i < NCH * 3; i += 64)
        wsh[i] = g_wpack[oc * (NCH * 3) + i];

    // x tile: rows h-1..h+1, cols -1..64, zero-padded
    const float* xb = x + (long)n * NCH * HH * WW;
    for (int idx = tid; idx < NCH * 3 * 66; idx += 64) {
        int c   = idx / 198;
        int rem = idx - c * 198;
        int r   = rem / 66;
        int col = rem - r * 66;
        int gh = h + r - 1;
        int gw = col - 1;
        float v = 0.0f;
        if ((unsigned)gh < HH && (unsigned)gw < WW)
            v = xb[(c * HH + gh) * WW + gw];
        tile[idx] = v;
    }
    __syncthreads();

    const int w0 = tid;  // output column; reads tile[... + w0 .. w0+2]

    float v3[3];
#pragma unroll
    for (int g3 = 0; g3 < 3; g3++) {
        float v9[3];
#pragma unroll
        for (int g9 = 0; g9 < 3; g9++) {
            float ch[3];
#pragma unroll
            for (int cc = 0; cc < 3; cc++) {
                int c = g3 * 9 + g9 * 3 + cc;
                float r[3];
#pragma unroll
                for (int ki = 0; ki < 3; ki++) {
                    const float* t = &tile[(c * 3 + ki) * 66 + w0];
                    float x0 = t[0], x1 = t[1], x2 = t[2];
                    float4 wv = wsh[c * 3 + ki];
                    // maj3(x0*w0, x1*w1, x2*w2) = 0.5*((x.w) - (x0x1x2)*(w0w1w2))
                    float s = x0 * wv.x + x1 * wv.y + x2 * wv.z;
                    float p = x0 * x1 * x2;
                    r[ki] = 0.5f * (s - p * wv.w);
                }
                ch[cc] = maj3(r[0], r[1], r[2]);
            }
            v9[g9] = maj3(ch[0], ch[1], ch[2]);
        }
        v3[g3] = maj3(v9[0], v9[1], v9[2]);
    }
    float res = maj3(v3[0], v3[1], v3[2]);

    out[(((long)n * OC + oc) * HH + h) * WW + w0] = res;
}

extern "C" void kernel_launch(void* const* d_in, const int* in_sizes, int n_in,
                              void* d_out, int out_size) {
    const float* x = (const float*)d_in[0];
    const float* w = (const float*)d_in[1];
    float* out = (float*)d_out;

    pack_weights_kernel<<<(OC * NCH * 3 + 255) / 256, 256>>>(w);

    dim3 grid(HH, OC, NB);
    sconv_kernel<<<grid, 64>>>(x, out);
}

// round 4
// speedup vs baseline: 2.2838x; 2.2838x over previous
#include <cuda_runtime.h>

#define NCH 27
#define HH 64
#define WW 64
#define OC 32
#define NB 2

// packed HALF-weights: per (oc, c, ki): {w0/2, w1/2, w2/2, w0*w1*w2/2}
__device__ float4 g_wpack[OC * NCH * 3];

__global__ void pack_weights_kernel(const float* __restrict__ w) {
    int i = blockIdx.x * blockDim.x + threadIdx.x;
    if (i < OC * NCH * 3) {
        const float* p = w + i * 3;
        float a = p[0], b = p[1], c = p[2];
        g_wpack[i] = make_float4(0.5f * a, 0.5f * b, 0.5f * c, 0.5f * a * b * c);
    }
}

__device__ __forceinline__ float maj3(float a, float b, float c) {
    return 0.5f * (a + b + c - a * b * c);
}

// grid (HH, OC/4, NB), 128 threads.
// thread -> pixel w0 = tid&63, oc lane = tid>>6 (0/1); each thread does ocs lane, lane+2.
__global__ __launch_bounds__(128, 6) void sconv_kernel(const float* __restrict__ x,
                                                       float* __restrict__ out) {
    __shared__ float tile[81 * 66];     // [row = c*3+r][col 0..65], col 0 & 65 = halo (always 0)
    __shared__ float4 wsh[4 * 81];      // 4 consecutive ocs

    const int h   = blockIdx.x;
    const int ocg = blockIdx.y;
    const int n   = blockIdx.z;
    const int tid = threadIdx.x;

    // weights: 4 consecutive ocs are contiguous in g_wpack
    for (int i = tid; i < 4 * 81; i += 128)
        wsh[i] = g_wpack[ocg * 4 * 81 + i];

    // halo columns: gw=-1 and gw=64 are ALWAYS outside the image -> zero
    for (int i = tid; i < 162; i += 128) {
        int row = i >> 1;
        tile[row * 66 + ((i & 1) ? 65 : 0)] = 0.0f;
    }

    // interior: 81 rows x 64 cols, shift/mask indexing only
    {
        const float* xb = x + (size_t)n * NCH * HH * WW;
        const int col = tid & 63;
        int row = tid >> 6;  // 0 or 1
#pragma unroll 4
        for (; row < 81; row += 2) {
            int c  = row / 3;            // const-divisor -> mul-high
            int r  = row - 3 * c;
            int gh = h + r - 1;
            float v = 0.0f;
            if ((unsigned)gh < (unsigned)HH)
                v = xb[c * (HH * WW) + gh * WW + col];
            tile[row * 66 + 1 + col] = v;
        }
    }
    __syncthreads();

    const int w0   = tid & 63;
    const int lane = tid >> 6;               // 0 or 1
    const float*  tb  = tile + w0;           // read tb[row*66 + 0..2]
    const float4* wp0 = wsh + lane * 81;     // oc_local = lane
    const float4* wp1 = wsh + (lane + 2) * 81;

    float a3a[3], a3b[3];
#pragma unroll
    for (int g3 = 0; g3 < 3; g3++) {
        float a9a[3], a9b[3];
#pragma unroll
        for (int g9 = 0; g9 < 3; g9++) {
            float cha[3], chb[3];
#pragma unroll
            for (int cc = 0; cc < 3; cc++) {
                const int c = g3 * 9 + g9 * 3 + cc;
                float ra[3], rb[3];
#pragma unroll
                for (int ki = 0; ki < 3; ki++) {
                    const float* t = tb + (c * 3 + ki) * 66;
                    float x0 = t[0], x1 = t[1], x2 = t[2];
                    float p = x0 * x1 * x2;          // shared across both ocs
                    float4 wa = wp0[c * 3 + ki];
                    float4 wb = wp1[c * 3 + ki];
                    // maj3 of leaf products, weights pre-scaled by 0.5
                    ra[ki] = x0 * wa.x + x1 * wa.y + x2 * wa.z - p * wa.w;
                    rb[ki] = x0 * wb.x + x1 * wb.y + x2 * wb.z - p * wb.w;
                }
                cha[cc] = maj3(ra[0], ra[1], ra[2]);
                chb[cc] = maj3(rb[0], rb[1], rb[2]);
            }
            a9a[g9] = maj3(cha[0], cha[1], cha[2]);
            a9b[g9] = maj3(chb[0], chb[1], chb[2]);
        }
        a3a[g3] = maj3(a9a[0], a9a[1], a9a[2]);
        a3b[g3] = maj3(a9b[0], a9b[1], a9b[2]);
    }
    float resa = maj3(a3a[0], a3a[1], a3a[2]);
    float resb = maj3(a3b[0], a3b[1], a3b[2]);

    const int oca = ocg * 4 + lane;
    const int ocb = oca + 2;
    out[(((size_t)n * OC + oca) * HH + h) * WW + w0] = resa;
    out[(((size_t)n * OC + ocb) * HH + h) * WW + w0] = resb;
}

extern "C" void kernel_launch(void* const* d_in, const int* in_sizes, int n_in,
                              void* d_out, int out_size) {
    const float* x = (const float*)d_in[0];
    const float* w = (const float*)d_in[1];
    float* out = (float*)d_out;

    pack_weights_kernel<<<(OC * NCH * 3 + 255) / 256, 256>>>(w);

    dim3 grid(HH, OC / 4, NB);
    sconv_kernel<<<grid, 128>>>(x, out);
}

// round 6
// speedup vs baseline: 2.5958x; 1.1366x over previous
#include <cuda_runtime.h>

#define NCH 27
#define HH 64
#define WW 64
#define OC 32
#define NB 2
#define PITCH 68   // tile row pitch (floats); 68 = 64 data + halo + pad, keeps 2p offsets 8B-aligned

__device__ __forceinline__ float maj3(float a, float b, float c) {
    return 0.5f * (a + b + c - a * b * c);
}

// grid (HH, OC/4, NB), 128 threads.
// thread -> pixel pair p = tid&31 (cols 2p, 2p+1), oc_local = tid>>5 (0..3).
__global__ __launch_bounds__(128, 8) void sconv_kernel(const float* __restrict__ x,
                                                       const float* __restrict__ wraw,
                                                       float* __restrict__ out) {
    __shared__ __align__(16) float tile[81 * PITCH]; // [row=c*3+r][col 0..65], col0/col65 = zero halo
    __shared__ float4 wsh[4 * 81];                   // packed half-weights for 4 ocs

    const int h   = blockIdx.x;
    const int ocg = blockIdx.y;
    const int n   = blockIdx.z;
    const int tid = threadIdx.x;

    // pack weights for the block's 4 ocs: {w0/2, w1/2, w2/2, w0w1w2/2}
    for (int i = tid; i < 4 * 81; i += 128) {
        int ol  = i / 81;
        int win = i - ol * 81;
        const float* pw = wraw + (ocg * 4 + ol) * 243 + win * 3;
        float a = pw[0], b = pw[1], c = pw[2];
        wsh[i] = make_float4(0.5f * a, 0.5f * b, 0.5f * c, 0.5f * a * b * c);
    }

    // halo columns (gw=-1, gw=64) are always outside the image -> zero
    for (int i = tid; i < 162; i += 128) {
        int row = i >> 1;
        tile[row * PITCH + ((i & 1) ? 65 : 0)] = 0.0f;
    }

    // interior: 81 rows x 64 cols
    {
        const float* xb = x + (size_t)n * NCH * HH * WW;
        const int col = tid & 63;
#pragma unroll 4
        for (int row = tid >> 6; row < 81; row += 2) {
            int c  = row / 3;
            int r  = row - 3 * c;
            int gh = h + r - 1;
            float v = 0.0f;
            if ((unsigned)gh < (unsigned)HH)
                v = xb[c * (HH * WW) + gh * WW + col];
            tile[row * PITCH + 1 + col] = v;
        }
    }
    __syncthreads();

    const int p  = tid & 31;        // pixel pair: output cols 2p, 2p+1
    const int ol = tid >> 5;        // oc within group (uniform per warp -> broadcast weight LDS)
    const float2* t2 = reinterpret_cast<const float2*>(tile);
    const float4* wp = wsh + ol * 81;

    float a3a[3], a3b[3];
#pragma unroll
    for (int g3 = 0; g3 < 3; g3++) {
        float a9a[3], a9b[3];
#pragma unroll
        for (int g9 = 0; g9 < 3; g9++) {
            float cha[3], chb[3];
#pragma unroll
            for (int cc = 0; cc < 3; cc++) {
                const int c = g3 * 9 + g9 * 3 + cc;
                float ra[3], rb[3];
#pragma unroll
                for (int ki = 0; ki < 3; ki++) {
                    const int row = c * 3 + ki;
                    float2 u = t2[row * (PITCH / 2) + p];       // v0, v1
                    float2 v = t2[row * (PITCH / 2) + p + 1];   // v2, v3
                    float4 wv = wp[row];
                    float m  = u.y * v.x;          // v1*v2, shared between pixels
                    float p0 = u.x * m;            // v0*v1*v2
                    float p1 = m * v.y;            // v1*v2*v3
                    // maj3 of leaf products (weights pre-scaled by 0.5)
                    ra[ki] = u.x * wv.x + u.y * wv.y + v.x * wv.z - p0 * wv.w;
                    rb[ki] = u.y * wv.x + v.x * wv.y + v.y * wv.z - p1 * wv.w;
                }
                cha[cc] = maj3(ra[0], ra[1], ra[2]);
                chb[cc] = maj3(rb[0], rb[1], rb[2]);
            }
            a9a[g9] = maj3(cha[0], cha[1], cha[2]);
            a9b[g9] = maj3(chb[0], chb[1], chb[2]);
        }
        a3a[g3] = maj3(a9a[0], a9a[1], a9a[2]);
        a3b[g3] = maj3(a9b[0], a9b[1], a9b[2]);
    }

    float2 res;
    res.x = maj3(a3a[0], a3a[1], a3a[2]);   // col 2p
    res.y = maj3(a3b[0], a3b[1], a3b[2]);   // col 2p+1

    const int oc = ocg * 4 + ol;
    float2* op = reinterpret_cast<float2*>(out + (((size_t)n * OC + oc) * HH + h) * WW);
    op[p] = res;
}

extern "C" void kernel_launch(void* const* d_in, const int* in_sizes, int n_in,
                              void* d_out, int out_size) {
    const float* x = (const float*)d_in[0];
    const float* w = (const float*)d_in[1];
    float* out = (float*)d_out;

    dim3 grid(HH, OC / 4, NB);
    sconv_kernel<<<grid, 128>>>(x, w, out);
}